// round 11
// baseline (speedup 1.0000x reference)
#include <cuda_runtime.h>
#include <cuda_bf16.h>
#include <math.h>

// ============================================================================
// VNETDetector: K1 NN+softmax -> HALVED llrs (parallel); K2 sequential ACS
// scan -- per step: 4x LDS.128 + 4x FFMA2(rt4?) + 8x FFMA-imm(rt1, mult=2.0,
// bit-exact add of pre-halved llrs) + 8x FMNMX, states as 8 scalars so mins
// write them directly; K3 bit-exact checkpoint replay (parallel).
// ============================================================================

#define T_CAP      250112               // multiple of 128 and 64, >= 250000
#define SEG_STEPS  128
#define NSEG       4                    // ring: 4 * 128 * 64B = 32 KB
#define CKPT_STRIDE 64

// llr rows stored interleaved per t, PRE-HALVED (lh = 0.5*llr, exact):
//   q0 = (l0,l1,l8,l9)h  q1 = (l2,l3,l10,l11)h
//   q2 = (l4,l5,l12,l13)h q3 = (l6,l7,l14,l15)h
__device__ __align__(16) float4 g_llr4[T_CAP * 4];                  // 16 MB
__device__ __align__(16) float4 g_ckpt[(T_CAP / CKPT_STRIDE) * 2];  // 32B per ckpt

// ---------------- scalar ACS step (tail path + K3 replay; bit-exact twin) ---
// fma.rn(lh, 2.0, w) = rn(2*lh + w) = rn(l + w): 2*lh is exact, single
// rounding -> identical to __fadd_rn(w, l) for all values here (l >= 0, no
// subnormal halving loss: smallest nonzero llr ~1e-7).
__device__ __forceinline__ void acs_step_scalar(
    float& w0, float& w1, float& w2, float& w3,
    float& w4, float& w5, float& w6, float& w7,
    float4 q0, float4 q1, float4 q2, float4 q3)
{
    float nw0 = fminf(__fmaf_rn(q0.x, 2.0f, w0), __fmaf_rn(q0.y, 2.0f, w1));
    float nw4 = fminf(__fmaf_rn(q0.z, 2.0f, w0), __fmaf_rn(q0.w, 2.0f, w1));
    float nw1 = fminf(__fmaf_rn(q1.x, 2.0f, w2), __fmaf_rn(q1.y, 2.0f, w3));
    float nw5 = fminf(__fmaf_rn(q1.z, 2.0f, w2), __fmaf_rn(q1.w, 2.0f, w3));
    float nw2 = fminf(__fmaf_rn(q2.x, 2.0f, w4), __fmaf_rn(q2.y, 2.0f, w5));
    float nw6 = fminf(__fmaf_rn(q2.z, 2.0f, w4), __fmaf_rn(q2.w, 2.0f, w5));
    float nw3 = fminf(__fmaf_rn(q3.x, 2.0f, w6), __fmaf_rn(q3.y, 2.0f, w7));
    float nw7 = fminf(__fmaf_rn(q3.z, 2.0f, w6), __fmaf_rn(q3.w, 2.0f, w7));
    w0 = nw0; w1 = nw1; w2 = nw2; w3 = nw3;
    w4 = nw4; w5 = nw5; w6 = nw6; w7 = nw7;
}

// One ACS step. States are scalar operands %0..%7 (w0..w7); %8 = smem addr
// of this step's 64B; %9 = packed (2.0f,2.0f) for the f32x2 ops.
// Low edges (l0..l7) via 4x fma.rn.f32x2 (pairs are natural: v4 load dests
// and state pairs). High edges (l8..l15) via 8x scalar fma.rn.f32 with
// IMMEDIATE multiplier 2.0 -> FFMA-imm form, rt_SMSP = 1.
#define ACS(o0, o1, o2, o3) \
  "{\n\t" \
  ".reg .f32 pa,pb,pc,pd,qa,qb,qc,qd,ra,rb,rc,rd,sa,sb,sc,sd;\n\t" \
  ".reg .b64 xa,xb,xc,xd,wa,wb,wc,wd,ta,tb,tc,td;\n\t" \
  ".reg .f32 ea,eb,ec,ed,ee,ef,eg,eh,fa,fb,fc,fd,fe,ff,fg,fh;\n\t" \
  "ld.shared.v4.f32 {pa,pb,pc,pd}, [%8+" o0 "];\n\t" \
  "ld.shared.v4.f32 {qa,qb,qc,qd}, [%8+" o1 "];\n\t" \
  "ld.shared.v4.f32 {ra,rb,rc,rd}, [%8+" o2 "];\n\t" \
  "ld.shared.v4.f32 {sa,sb,sc,sd}, [%8+" o3 "];\n\t" \
  "mov.b64 xa, {pa,pb};\n\t" \
  "mov.b64 xb, {qa,qb};\n\t" \
  "mov.b64 xc, {ra,rb};\n\t" \
  "mov.b64 xd, {sa,sb};\n\t" \
  "mov.b64 wa, {%0,%1};\n\t" \
  "mov.b64 wb, {%2,%3};\n\t" \
  "mov.b64 wc, {%4,%5};\n\t" \
  "mov.b64 wd, {%6,%7};\n\t" \
  "fma.rn.f32x2 ta, xa, %9, wa;\n\t" \
  "fma.rn.f32x2 tb, xb, %9, wb;\n\t" \
  "fma.rn.f32x2 tc, xc, %9, wc;\n\t" \
  "fma.rn.f32x2 td, xd, %9, wd;\n\t" \
  "fma.rn.f32 ea, pc, 0f40000000, %0;\n\t" \
  "fma.rn.f32 eb, pd, 0f40000000, %1;\n\t" \
  "fma.rn.f32 ec, qc, 0f40000000, %2;\n\t" \
  "fma.rn.f32 ed, qd, 0f40000000, %3;\n\t" \
  "fma.rn.f32 ee, rc, 0f40000000, %4;\n\t" \
  "fma.rn.f32 ef, rd, 0f40000000, %5;\n\t" \
  "fma.rn.f32 eg, sc, 0f40000000, %6;\n\t" \
  "fma.rn.f32 eh, sd, 0f40000000, %7;\n\t" \
  "mov.b64 {fa,fb}, ta;\n\t" \
  "mov.b64 {fc,fd}, tb;\n\t" \
  "mov.b64 {fe,ff}, tc;\n\t" \
  "mov.b64 {fg,fh}, td;\n\t" \
  "min.f32 %0, fa, fb;\n\t" \
  "min.f32 %1, fc, fd;\n\t" \
  "min.f32 %2, fe, ff;\n\t" \
  "min.f32 %3, fg, fh;\n\t" \
  "min.f32 %4, ea, eb;\n\t" \
  "min.f32 %5, ec, ed;\n\t" \
  "min.f32 %6, ee, ef;\n\t" \
  "min.f32 %7, eg, eh;\n\t" \
  "}\n\t"

// 16 steps = 1024 bytes of llr data, one asm block, scalar states.
#define ACS16(W0,W1,W2,W3,W4,W5,W6,W7, SADDR, TWO2)                        \
  asm volatile(                                                            \
      ACS("0","16","32","48")       ACS("64","80","96","112")              \
      ACS("128","144","160","176")  ACS("192","208","224","240")           \
      ACS("256","272","288","304")  ACS("320","336","352","368")           \
      ACS("384","400","416","432")  ACS("448","464","480","496")           \
      ACS("512","528","544","560")  ACS("576","592","608","624")           \
      ACS("640","656","672","688")  ACS("704","720","736","752")           \
      ACS("768","784","800","816")  ACS("832","848","864","880")           \
      ACS("896","912","928","944")  ACS("960","976","992","1008")          \
      : "+f"(W0), "+f"(W1), "+f"(W2), "+f"(W3),                            \
        "+f"(W4), "+f"(W5), "+f"(W6), "+f"(W7)                             \
      : "r"(SADDR), "l"(TWO2)                                              \
      : "memory")

// ============================================================================
// K1: per-t NN forward, log_softmax -> HALVED llrs, argmax bit + max prob
// ============================================================================
__global__ __launch_bounds__(128)
void k1_llr(const float* __restrict__ rx,
            const float* __restrict__ W1, const float* __restrict__ b1,
            const float* __restrict__ W2, const float* __restrict__ b2,
            float* __restrict__ out_cbits, float* __restrict__ out_conf, int T)
{
    __shared__ float sW1[100], sb1[100], sW2[1600], sb2[16];
    for (int k = threadIdx.x; k < 100;  k += blockDim.x) { sW1[k] = W1[k]; sb1[k] = b1[k]; }
    for (int k = threadIdx.x; k < 1600; k += blockDim.x) { sW2[k] = W2[k]; }
    for (int k = threadIdx.x; k < 16;   k += blockDim.x) { sb2[k] = b2[k]; }
    __syncthreads();

    int t = blockIdx.x * blockDim.x + threadIdx.x;
    if (t >= T) return;

    float x = rx[t];

    float acc[16];
#pragma unroll
    for (int i = 0; i < 16; i++) acc[i] = 0.0f;

#pragma unroll 4
    for (int j = 0; j < 100; j++) {
        float h = fmaxf(__fadd_rn(__fmul_rn(x, sW1[j]), sb1[j]), 0.0f);
#pragma unroll
        for (int i = 0; i < 16; i++)
            acc[i] = __fmaf_rn(h, sW2[i * 100 + j], acc[i]);
    }
#pragma unroll
    for (int i = 0; i < 16; i++) acc[i] = __fadd_rn(acc[i], sb2[i]);

    float m = acc[0];
#pragma unroll
    for (int i = 1; i < 16; i++) m = fmaxf(m, acc[i]);

    float sh[16];
    float S = 0.0f;
#pragma unroll
    for (int i = 0; i < 16; i++) {
        sh[i] = __fadd_rn(acc[i], -m);
        S = __fadd_rn(S, expf(sh[i]));
    }
    float lse = logf(S);

    float lh[16];          // HALVED llrs (exact: llr * 0.5)
    float best = -1.0f;
    int bi = 0;
#pragma unroll
    for (int i = 0; i < 16; i++) {
        float lp = __fadd_rn(sh[i], -lse);
        lh[i] = __fmul_rn(-lp, 0.5f);
        float p = expf(lp);
        if (p > best) { best = p; bi = i; }   // strict > keeps first occurrence
    }

    out_cbits[t] = (float)(bi & 1);
    out_conf[t]  = best;

    float4* dst = g_llr4 + (size_t)t * 4;
    dst[0] = make_float4(lh[0], lh[1], lh[8],  lh[9]);
    dst[1] = make_float4(lh[2], lh[3], lh[10], lh[11]);
    dst[2] = make_float4(lh[4], lh[5], lh[12], lh[13]);
    dst[3] = make_float4(lh[6], lh[7], lh[14], lh[15]);
}

// ============================================================================
// K2: sequential ACS scan. 1 block, 128 threads.
//   warp 0 / lane 0 : consumer chain (SMSP 0, exclusive issue port)
//   warps 1..3      : producers (fill llr ring + flush checkpoint slots)
// ============================================================================
__global__ __launch_bounds__(128, 1)
void k2_scan(int T)
{
    __shared__ __align__(16) float4 ring[NSEG * SEG_STEPS * 4];      // 32 KB
    __shared__ __align__(16) float4 ck_smem[NSEG * 4];               // 2 ckpts*32B per slot
    __shared__ volatile int s_ready[NSEG];
    __shared__ volatile int s_freed[NSEG];

    int tid  = threadIdx.x;
    int wid  = tid >> 5;
    int lane = tid & 31;

    if (tid < NSEG) { s_ready[tid] = 0; s_freed[tid] = 0; }
    __syncthreads();

    int nSegs = (T + SEG_STEPS - 1) / SEG_STEPS;

    if (wid >= 1) {
        // ------------------ producers ------------------
        for (int s = wid - 1; s < nSegs; s += 3) {
            int slot = s & (NSEG - 1);
            if (lane == 0) {
                while (s_freed[slot] < s + 1 - NSEG) __nanosleep(64);
            }
            __syncwarp();
            // flush checkpoints of the seg that last used this slot (consumer
            // finished it before raising s_freed, so ck_smem[slot] is final).
            if (s >= NSEG && lane < 8) {
                const unsigned long long* cs =
                    reinterpret_cast<const unsigned long long*>(ck_smem + slot * 4);
                unsigned long long* cg =
                    reinterpret_cast<unsigned long long*>(g_ckpt) + (size_t)(s - NSEG) * 8;
                cg[lane] = cs[lane];
            }
            const float4* src = g_llr4 + (size_t)s * SEG_STEPS * 4;
            float4* dst = ring + slot * SEG_STEPS * 4;
#pragma unroll
            for (int k = 0; k < (SEG_STEPS * 4) / 32; k++)
                dst[k * 32 + lane] = src[k * 32 + lane];
            __syncwarp();
            __threadfence_block();
            if (lane == 0) s_ready[slot] = s + 1;
        }
    } else if (tid == 0) {
        // ------------------ consumer (the chain) ------------------
        float w0 = 0.f, w1 = 0.f, w2 = 0.f, w3 = 0.f;
        float w4 = 0.f, w5 = 0.f, w6 = 0.f, w7 = 0.f;
        const unsigned long long TWO2 = 0x4000000040000000ULL;   // (2.0f, 2.0f)

        unsigned ring0 = (unsigned)__cvta_generic_to_shared(ring);

        for (int s = 0; s < nSegs; s++) {
            int slot = s & (NSEG - 1);
            while (s_ready[slot] < s + 1) { /* spin */ }

            unsigned saddr = ring0 + slot * (SEG_STEPS * 64);
            float4* ckb = ck_smem + slot * 4;
            int steps = min(SEG_STEPS, T - s * SEG_STEPS);

            if (steps == SEG_STEPS) {
                // 8 blocks of 16 steps; ckpt every 64 steps
#pragma unroll 1
                for (int blk = 0; blk < 8; blk++) {
                    if ((blk & 3) == 0) {
                        int c = (blk >> 2) * 2;
                        ckb[c + 0] = make_float4(w0, w1, w2, w3);
                        ckb[c + 1] = make_float4(w4, w5, w6, w7);
                    }
                    ACS16(w0, w1, w2, w3, w4, w5, w6, w7,
                          saddr + blk * 1024, TWO2);
                }
            } else {
                // ---- tail seg (steps < 128, multiple of 16 for T=250000) ----
                const float4* sp = ring + slot * SEG_STEPS * 4;
                for (int j = 0; j < steps; j++) {
                    if ((j & 63) == 0) {
                        int c = (j >> 6) * 2;
                        ckb[c + 0] = make_float4(w0, w1, w2, w3);
                        ckb[c + 1] = make_float4(w4, w5, w6, w7);
                    }
                    const float4* q = sp + j * 4;
                    acs_step_scalar(w0, w1, w2, w3, w4, w5, w6, w7,
                                    q[0], q[1], q[2], q[3]);
                }
            }

            s_freed[slot] = s + 1;
        }

        // flush checkpoints of the last up-to-NSEG segs (their slots are never
        // reused by a producer)
        int s0 = (nSegs > NSEG) ? (nSegs - NSEG) : 0;
        for (int s = s0; s < nSegs; s++) {
            int slot = s & (NSEG - 1);
            const unsigned long long* cs =
                reinterpret_cast<const unsigned long long*>(ck_smem + slot * 4);
            unsigned long long* cg =
                reinterpret_cast<unsigned long long*>(g_ckpt) + (size_t)s * 8;
            for (int k = 0; k < 8; k++) cg[k] = cs[k];
        }
    }
}

// ============================================================================
// K3: replay each 64-step chunk from its checkpoint, emit detected bits.
// Bit-exact: __fmaf_rn(lh,2,w) == consumer's FFMA ops, same order.
// ============================================================================
__global__ __launch_bounds__(128)
void k3_bits(float* __restrict__ out_bits, int T)
{
    int c = blockIdx.x * blockDim.x + threadIdx.x;
    int t0 = c * CKPT_STRIDE;
    if (t0 >= T) return;

    float4 c0 = g_ckpt[(size_t)c * 2 + 0];
    float4 c1 = g_ckpt[(size_t)c * 2 + 1];
    float w0 = c0.x, w1 = c0.y, w2 = c0.z, w3 = c0.w;
    float w4 = c1.x, w5 = c1.y, w6 = c1.z, w7 = c1.w;

    int n = min(CKPT_STRIDE, T - t0);
    for (int j = 0; j < n; j++) {
        float best = w0; int bi = 0;
        if (w1 < best) { best = w1; bi = 1; }
        if (w2 < best) { best = w2; bi = 2; }
        if (w3 < best) { best = w3; bi = 3; }
        if (w4 < best) { best = w4; bi = 4; }
        if (w5 < best) { best = w5; bi = 5; }
        if (w6 < best) { best = w6; bi = 6; }
        if (w7 < best) { best = w7; bi = 7; }
        out_bits[t0 + j] = (float)(bi & 1);

        const float4* q = g_llr4 + (size_t)(t0 + j) * 4;
        acs_step_scalar(w0, w1, w2, w3, w4, w5, w6, w7,
                        q[0], q[1], q[2], q[3]);
    }
}

// ============================================================================
extern "C" void kernel_launch(void* const* d_in, const int* in_sizes, int n_in,
                              void* d_out, int out_size)
{
    const float* rx = (const float*)d_in[0];
    const float* W1 = (const float*)d_in[1];
    const float* b1 = (const float*)d_in[2];
    const float* W2 = (const float*)d_in[3];
    const float* b2 = (const float*)d_in[4];
    int T = in_sizes[0];

    float* out = (float*)d_out;
    int sections = (T > 0) ? (out_size / T) : 0;
    float* out_det = out;
    float* out_cb  = (sections >= 2) ? out + T     : out;
    float* out_cw  = (sections >= 3) ? out + 2 * T : out_cb;

    int grid1 = (T + 127) / 128;
    k1_llr<<<grid1, 128>>>(rx, W1, b1, W2, b2, out_cb, out_cw, T);

    k2_scan<<<1, 128>>>(T);

    int nChunks = (T + CKPT_STRIDE - 1) / CKPT_STRIDE;
    int grid3 = (nChunks + 127) / 128;
    k3_bits<<<grid3, 128>>>(out_det, T);
}